// round 1
// baseline (speedup 1.0000x reference)
#include <cuda_runtime.h>
#include <cuda_bf16.h>
#include <cstdint>

#define BATCH 64
#define NNODE 50
#define FDIM 64
#define HDIM 128
#define EDGES 2450           // 50*49
#define TSTEPS 40
#define PS 136               // padded bf16 stride for 128-wide tiles (conflict-free)
#define CHUNK 128
#define EDGES_PER_CTA 1225   // 25 receivers * 49
#define NCHUNK 10            // ceil(1225/128)

// ---------------- device scratch (no allocations allowed) ----------------
__device__ float          g_y[BATCH*NNODE*FDIM];
__device__ float          g_ksum[BATCH*NNODE*FDIM];
__device__ __nv_bfloat16  g_ybf[BATCH*NNODE*FDIM];
__device__ float          g_agg[BATCH*NNODE*HDIM];
__device__ __nv_bfloat16  g_Wt[4*HDIM*PS];   // [slot][n][k], slot: 0,1=W1^T(k0,k1) 2,3=W2^T

// ---------------- helpers ----------------
__device__ __forceinline__ void mma16816(float c[4], const uint32_t a[4], const uint32_t b[2]) {
    asm volatile(
        "mma.sync.aligned.m16n8k16.row.col.f32.bf16.bf16.f32 "
        "{%0,%1,%2,%3}, {%4,%5,%6,%7}, {%8,%9}, {%0,%1,%2,%3};\n"
        : "+f"(c[0]), "+f"(c[1]), "+f"(c[2]), "+f"(c[3])
        : "r"(a[0]), "r"(a[1]), "r"(a[2]), "r"(a[3]), "r"(b[0]), "r"(b[1]));
}

__device__ __forceinline__ uint32_t packbf(float x, float y) {
    __nv_bfloat162 t = __floats2bfloat162_rn(x, y);
    return *reinterpret_cast<uint32_t*>(&t);
}

struct SmemA {
    __nv_bfloat16 W[4][HDIM*PS];       // weights, [n*PS + k]
    __nv_bfloat16 pre[CHUNK*PS];       // pre tile, later reused as m tile
    __nv_bfloat16 hbuf[CHUNK*PS];      // gated hidden tile
    __nv_bfloat16 y[NNODE*FDIM];       // current batch node features (bf16)
    float B1[2*HDIM];
    float B2[2*HDIM];
    int   Kt[CHUNK];                   // edge type per row (-1 invalid)
    int   Rt[CHUNK];                   // receiver per row (-1 invalid)
};

// GEMM: C[16][4] += A[128,128] (rows wm..wm+63) @ Wt^T tile (cols wn..wn+31)
__device__ __forceinline__ void gemm128(const __nv_bfloat16* __restrict__ A,
                                        const __nv_bfloat16* __restrict__ Wt,
                                        float (*C)[4], int wm, int wn, int g, int tig) {
#pragma unroll
    for (int kb = 0; kb < 8; ++kb) {
        const int k0 = kb*16 + 2*tig;
        uint32_t a[4][4];
#pragma unroll
        for (int mt = 0; mt < 4; ++mt) {
            const __nv_bfloat16* b0 = A + (wm + mt*16 + g)*PS + k0;
            const __nv_bfloat16* b1 = b0 + 8*PS;
            a[mt][0] = *reinterpret_cast<const uint32_t*>(b0);
            a[mt][1] = *reinterpret_cast<const uint32_t*>(b1);
            a[mt][2] = *reinterpret_cast<const uint32_t*>(b0 + 8);
            a[mt][3] = *reinterpret_cast<const uint32_t*>(b1 + 8);
        }
        uint32_t bfr[4][2];
#pragma unroll
        for (int nt = 0; nt < 4; ++nt) {
            const __nv_bfloat16* wb = Wt + (wn + nt*8 + g)*PS + k0;
            bfr[nt][0] = *reinterpret_cast<const uint32_t*>(wb);
            bfr[nt][1] = *reinterpret_cast<const uint32_t*>(wb + 8);
        }
#pragma unroll
        for (int mt = 0; mt < 4; ++mt)
#pragma unroll
            for (int nt = 0; nt < 4; ++nt)
                mma16816(C[mt*4 + nt], a[mt], bfr[nt]);
    }
}

// ---------------- prep: weights->bf16 transposed-padded, init state ----------------
__global__ void prep_kernel(const float* __restrict__ fp,
                            const float* __restrict__ W1,
                            const float* __restrict__ W2,
                            float* __restrict__ out) {
    int gsz = gridDim.x * blockDim.x;
    int g0  = blockIdx.x * blockDim.x + threadIdx.x;
    // weights: Wt[slot][n][k] = Wsrc[kk][k][n]
    for (int i = g0; i < 4*HDIM*HDIM; i += gsz) {
        int slot = i >> 14;
        int rem  = i & 16383;
        int n = rem >> 7, k = rem & 127;
        float v = (slot < 2) ? W1[slot*HDIM*HDIM + k*HDIM + n]
                             : W2[(slot-2)*HDIM*HDIM + k*HDIM + n];
        g_Wt[slot*(HDIM*PS) + n*PS + k] = __float2bfloat16(v);
    }
    // y0, bf16 copy, out[:, t=0, :]
    for (int i = g0; i < BATCH*NNODE*FDIM; i += gsz) {
        float v = fp[i];
        g_y[i]   = v;
        g_ybf[i] = __float2bfloat16(v);
        out[(i >> 6)*(TSTEPS*FDIM) + (i & 63)] = v;
    }
    for (int i = g0; i < BATCH*NNODE*HDIM; i += gsz) g_agg[i] = 0.f;
}

// ---------------- edge kernel: fused gather + 2-layer gated MLP + aggregate ----------------
__global__ void __launch_bounds__(256, 1)
edge_kernel(const int* __restrict__ graph,
            const float* __restrict__ b1,
            const float* __restrict__ b2) {
    extern __shared__ char smem_raw[];
    SmemA* sm = reinterpret_cast<SmemA*>(smem_raw);
    const int tid = threadIdx.x;
    const int b   = blockIdx.x >> 1;
    const int hb  = blockIdx.x & 1;          // which half of receivers

    // load weights (139 KB) + y[b] + biases to SMEM
    {
        const uint4* src = reinterpret_cast<const uint4*>(g_Wt);
        uint4* dst = reinterpret_cast<uint4*>(&sm->W[0][0]);
        for (int i = tid; i < 4*HDIM*PS/8; i += 256) dst[i] = src[i];
    }
    {
        const uint4* src = reinterpret_cast<const uint4*>(g_ybf + b*NNODE*FDIM);
        uint4* dst = reinterpret_cast<uint4*>(&sm->y[0]);
        for (int i = tid; i < NNODE*FDIM/8; i += 256) dst[i] = src[i];
    }
    sm->B1[tid] = b1[tid];
    sm->B2[tid] = b2[tid];
    __syncthreads();

    const int lane = tid & 31, wid = tid >> 5;
    const int g = lane >> 2, tig = lane & 3;
    const int wm = (wid & 1) * 64;           // 2 warps along M
    const int wn = (wid >> 1) * 32;          // 4 warps along N
    const int ebase = hb * EDGES_PER_CTA;

    for (int ch = 0; ch < NCHUNK; ++ch) {
        const int nvalid = min(CHUNK, EDGES_PER_CTA - ch*CHUNK);

        // row metadata
        if (tid < CHUNK) {
            int row = tid, eloc = ch*CHUNK + row;
            if (eloc < EDGES_PER_CTA) {
                int e = ebase + eloc;
                int r = e / 49;
                sm->Kt[row] = graph[b*EDGES + e];
                sm->Rt[row] = r;
            } else { sm->Kt[row] = -1; sm->Rt[row] = -1; }
        }
        // build pre tile: [send feat | recv feat], 2 threads per row
        {
            int row = tid >> 1, hlf = tid & 1;
            int eloc = ch*CHUNK + row;
            uint4* dst = reinterpret_cast<uint4*>(&sm->pre[row*PS + hlf*64]);
            if (eloc < EDGES_PER_CTA) {
                int e = ebase + eloc;
                int r = e / 49, j = e - r*49;
                int s = j + (j >= r);
                int node = hlf ? r : s;
                const uint4* src = reinterpret_cast<const uint4*>(&sm->y[node*FDIM]);
#pragma unroll
                for (int q = 0; q < 8; ++q) dst[q] = src[q];
            } else {
                uint4 z = make_uint4(0,0,0,0);
#pragma unroll
                for (int q = 0; q < 8; ++q) dst[q] = z;
            }
        }
        __syncthreads();

        float C2[16][4];
#pragma unroll
        for (int i = 0; i < 16; ++i)
#pragma unroll
            for (int q = 0; q < 4; ++q) C2[i][q] = 0.f;

#pragma unroll
        for (int kk = 0; kk < 2; ++kk) {
            float C1[16][4];
#pragma unroll
            for (int i = 0; i < 16; ++i)
#pragma unroll
                for (int q = 0; q < 4; ++q) C1[i][q] = 0.f;

            gemm128(sm->pre, sm->W[kk], C1, wm, wn, g, tig);

            // epilogue: relu(+b1), gate rows by edge type, write bf16 h
#pragma unroll
            for (int mt = 0; mt < 4; ++mt)
#pragma unroll
                for (int nt = 0; nt < 4; ++nt) {
                    int r0 = wm + mt*16 + g, r1 = r0 + 8;
                    int c0 = wn + nt*8 + 2*tig;
                    float bias0 = sm->B1[kk*HDIM + c0];
                    float bias1 = sm->B1[kk*HDIM + c0 + 1];
                    float* c = C1[mt*4 + nt];
                    float v00 = fmaxf(c[0] + bias0, 0.f), v01 = fmaxf(c[1] + bias1, 0.f);
                    float v10 = fmaxf(c[2] + bias0, 0.f), v11 = fmaxf(c[3] + bias1, 0.f);
                    if (sm->Kt[r0] != kk) { v00 = 0.f; v01 = 0.f; }
                    if (sm->Kt[r1] != kk) { v10 = 0.f; v11 = 0.f; }
                    *reinterpret_cast<uint32_t*>(&sm->hbuf[r0*PS + c0]) = packbf(v00, v01);
                    *reinterpret_cast<uint32_t*>(&sm->hbuf[r1*PS + c0]) = packbf(v10, v11);
                }
            __syncthreads();

            gemm128(sm->hbuf, sm->W[2 + kk], C2, wm, wn, g, tig);
            __syncthreads();
        }

        // m epilogue: relu(C2 + b2[k_row]), write bf16 into pre-buffer (now free)
#pragma unroll
        for (int mt = 0; mt < 4; ++mt)
#pragma unroll
            for (int nt = 0; nt < 4; ++nt) {
                int r0 = wm + mt*16 + g, r1 = r0 + 8;
                int c0 = wn + nt*8 + 2*tig;
                float* c = C2[mt*4 + nt];
                int k0r = sm->Kt[r0], k1r = sm->Kt[r1];
                float v00 = 0.f, v01 = 0.f, v10 = 0.f, v11 = 0.f;
                if (k0r >= 0) {
                    v00 = fmaxf(c[0] + sm->B2[k0r*HDIM + c0], 0.f);
                    v01 = fmaxf(c[1] + sm->B2[k0r*HDIM + c0 + 1], 0.f);
                }
                if (k1r >= 0) {
                    v10 = fmaxf(c[2] + sm->B2[k1r*HDIM + c0], 0.f);
                    v11 = fmaxf(c[3] + sm->B2[k1r*HDIM + c0 + 1], 0.f);
                }
                *reinterpret_cast<uint32_t*>(&sm->pre[r0*PS + c0]) = packbf(v00, v01);
                *reinterpret_cast<uint32_t*>(&sm->pre[r1*PS + c0]) = packbf(v10, v11);
            }
        __syncthreads();

        // segmented aggregation over receiver runs (rows sorted by receiver)
        {
            int colT = tid & 127;
            int rbeg = (tid < 128) ? 0 : 64;
            int rend = (tid < 128) ? min(64, nvalid) : nvalid;
            float acc = 0.f; int cur = -1;
            for (int row = rbeg; row < rend; ++row) {
                int rr = sm->Rt[row];
                if (rr != cur) {
                    if (cur >= 0) atomicAdd(&g_agg[(b*NNODE + cur)*HDIM + colT], acc);
                    acc = 0.f; cur = rr;
                }
                acc += __bfloat162float(sm->pre[row*PS + colT]);
            }
            if (cur >= 0) atomicAdd(&g_agg[(b*NNODE + cur)*HDIM + colT], acc);
        }
        __syncthreads();
    }
}

// ---------------- node kernel: tanh(agg*inv_n @ W3 + b3) + RK4 stage update ----------------
__global__ void __launch_bounds__(256)
node_kernel(const float* __restrict__ ts, int t, int stage,
            const float* __restrict__ W3, const float* __restrict__ b3,
            float* __restrict__ out) {
    __shared__ float sW3[HDIM*FDIM];
    __shared__ float sb3[FDIM];
    __shared__ float sAgg[8][HDIM];
    int tid = threadIdx.x;
    for (int i = tid; i < HDIM*FDIM; i += 256) sW3[i] = W3[i];
    if (tid < FDIM) sb3[tid] = b3[tid];
    __syncthreads();

    int lane = tid & 31, wid = tid >> 5;
    int node = blockIdx.x * 8 + wid;

#pragma unroll
    for (int i = 0; i < 4; ++i) {
        int idx = node*HDIM + lane + i*32;
        float v = g_agg[idx];
        g_agg[idx] = 0.f;                    // zero for next eval
        sAgg[wid][lane + i*32] = v;
    }
    __syncwarp();

    float dt = ts[t+1] - ts[t];
    const float inv_n = 1.0f / (float)NNODE;

#pragma unroll
    for (int hlf = 0; hlf < 2; ++hlf) {
        int jj = lane + hlf*32;
        float acc = 0.f;
#pragma unroll 16
        for (int hh = 0; hh < HDIM; ++hh)
            acc = fmaf(sAgg[wid][hh], sW3[hh*FDIM + jj], acc);
        float kv = tanhf(acc * inv_n + sb3[jj]);
        int idx = node*FDIM + jj;
        float yv = g_y[idx];
        float yin;
        if (stage == 0)      { g_ksum[idx] = kv;          yin = yv + 0.5f*dt*kv; }
        else if (stage == 1) { g_ksum[idx] += 2.f*kv;     yin = yv + 0.5f*dt*kv; }
        else if (stage == 2) { g_ksum[idx] += 2.f*kv;     yin = yv + dt*kv; }
        else {
            float yn = yv + dt*(1.f/6.f)*(g_ksum[idx] + kv);
            g_y[idx] = yn;
            out[node*(TSTEPS*FDIM) + (t+1)*FDIM + jj] = yn;
            yin = yn;
        }
        g_ybf[idx] = __float2bfloat16(yin);
    }
}

// ---------------- launcher ----------------
extern "C" void kernel_launch(void* const* d_in, const int* in_sizes, int n_in,
                              void* d_out, int out_size) {
    const float* fp    = (const float*)d_in[0];
    const float* ts    = (const float*)d_in[1];
    const int*   graph = (const int*)d_in[2];
    const float* W1    = (const float*)d_in[3];
    const float* b1    = (const float*)d_in[4];
    const float* W2    = (const float*)d_in[5];
    const float* b2    = (const float*)d_in[6];
    const float* W3    = (const float*)d_in[7];
    const float* b3    = (const float*)d_in[8];
    float* out = (float*)d_out;

    const size_t smem = sizeof(SmemA);
    cudaFuncSetAttribute(edge_kernel, cudaFuncAttributeMaxDynamicSharedMemorySize, (int)smem);

    prep_kernel<<<256, 256>>>(fp, W1, W2, out);
    for (int t = 0; t < TSTEPS - 1; ++t) {
        for (int st = 0; st < 4; ++st) {
            edge_kernel<<<128, 256, smem>>>(graph, b1, b2);
            node_kernel<<<400, 256>>>(ts, t, st, W3, b3, out);
        }
    }
}

// round 2
// speedup vs baseline: 1.2844x; 1.2844x over previous
#include <cuda_runtime.h>
#include <cuda_bf16.h>
#include <cstdint>

#define BATCH 64
#define NNODE 50
#define FDIM 64
#define HDIM 128
#define EDGES 2450           // 50*49
#define TSTEPS 40
#define PS 136               // padded bf16 stride (conflict-free 128-wide tiles)
#define CHUNK 128
#define EPC 1225             // edges per CTA (half of batch's edges)
#define MAXROWS 1536         // <= 1225 + 2*127 padding, rounded to chunks

// ---------------- device scratch (no allocations allowed) ----------------
__device__ float          g_y[BATCH*NNODE*FDIM];
__device__ float          g_ksum[BATCH*NNODE*FDIM];
__device__ __nv_bfloat16  g_ybf[BATCH*NNODE*FDIM];
__device__ float          g_agg[BATCH*NNODE*HDIM];
__device__ __nv_bfloat16  g_Wt[4*HDIM*PS];   // [slot][n][k], slot: 0,1=W1^T(k0,k1) 2,3=W2^T
__device__ int            g_rows[128*MAXROWS]; // per-CTA sorted+padded edge meta
__device__ int            g_nrows[128];        // per-CTA row count (multiple of 128)

// ---------------- helpers ----------------
__device__ __forceinline__ void mma16816(float c[4], const uint32_t a[4], const uint32_t b[2]) {
    asm volatile(
        "mma.sync.aligned.m16n8k16.row.col.f32.bf16.bf16.f32 "
        "{%0,%1,%2,%3}, {%4,%5,%6,%7}, {%8,%9}, {%0,%1,%2,%3};\n"
        : "+f"(c[0]), "+f"(c[1]), "+f"(c[2]), "+f"(c[3])
        : "r"(a[0]), "r"(a[1]), "r"(a[2]), "r"(a[3]), "r"(b[0]), "r"(b[1]));
}

__device__ __forceinline__ uint32_t packbf(float x, float y) {
    __nv_bfloat162 t = __floats2bfloat162_rn(x, y);
    return *reinterpret_cast<uint32_t*>(&t);
}

struct SmemA {
    __nv_bfloat16 W[4][HDIM*PS];       // weights, [n*PS + k]        139264 B
    __nv_bfloat16 pre[CHUNK*PS];       // pre tile / m tile           34816 B
    __nv_bfloat16 hbuf[CHUNK*PS];      // hidden tile                 34816 B
    __nv_bfloat16 y[NNODE*FDIM];       // current batch node feats     6400 B
    float B1[2*HDIM];
    float B2[2*HDIM];
    int   Rt[CHUNK];                   // receiver per row (-1 pad)
    int   ck;                          // chunk edge type
};

// GEMM: C[16][4] += A[128,128] (rows wm..wm+63) @ Wt^T tile (cols wn..wn+31)
__device__ __forceinline__ void gemm128(const __nv_bfloat16* __restrict__ A,
                                        const __nv_bfloat16* __restrict__ Wt,
                                        float (*C)[4], int wm, int wn, int g, int tig) {
#pragma unroll
    for (int kb = 0; kb < 8; ++kb) {
        const int k0 = kb*16 + 2*tig;
        uint32_t a[4][4];
#pragma unroll
        for (int mt = 0; mt < 4; ++mt) {
            const __nv_bfloat16* b0 = A + (wm + mt*16 + g)*PS + k0;
            const __nv_bfloat16* b1 = b0 + 8*PS;
            a[mt][0] = *reinterpret_cast<const uint32_t*>(b0);
            a[mt][1] = *reinterpret_cast<const uint32_t*>(b1);
            a[mt][2] = *reinterpret_cast<const uint32_t*>(b0 + 8);
            a[mt][3] = *reinterpret_cast<const uint32_t*>(b1 + 8);
        }
        uint32_t bfr[4][2];
#pragma unroll
        for (int nt = 0; nt < 4; ++nt) {
            const __nv_bfloat16* wb = Wt + (wn + nt*8 + g)*PS + k0;
            bfr[nt][0] = *reinterpret_cast<const uint32_t*>(wb);
            bfr[nt][1] = *reinterpret_cast<const uint32_t*>(wb + 8);
        }
#pragma unroll
        for (int mt = 0; mt < 4; ++mt)
#pragma unroll
            for (int nt = 0; nt < 4; ++nt)
                mma16816(C[mt*4 + nt], a[mt], bfr[nt]);
    }
}

// ---------------- prep: weights->bf16 transposed-padded, init state ----------------
__global__ void prep_kernel(const float* __restrict__ fp,
                            const float* __restrict__ W1,
                            const float* __restrict__ W2,
                            float* __restrict__ out) {
    int gsz = gridDim.x * blockDim.x;
    int g0  = blockIdx.x * blockDim.x + threadIdx.x;
    for (int i = g0; i < 4*HDIM*HDIM; i += gsz) {
        int slot = i >> 14;
        int rem  = i & 16383;
        int n = rem >> 7, k = rem & 127;
        float v = (slot < 2) ? W1[slot*HDIM*HDIM + k*HDIM + n]
                             : W2[(slot-2)*HDIM*HDIM + k*HDIM + n];
        g_Wt[slot*(HDIM*PS) + n*PS + k] = __float2bfloat16(v);
    }
    for (int i = g0; i < BATCH*NNODE*FDIM; i += gsz) {
        float v = fp[i];
        g_y[i]   = v;
        g_ybf[i] = __float2bfloat16(v);
        out[(i >> 6)*(TSTEPS*FDIM) + (i & 63)] = v;
    }
    for (int i = g0; i < BATCH*NNODE*HDIM; i += gsz) g_agg[i] = 0.f;
}

// ---------------- sort: stable partition of each CTA's edges by type, padded ----------------
// One warp per CTA. Warp-ballot stream compaction preserves receiver-major order.
__global__ void sort_kernel(const int* __restrict__ graph) {
    const int cta  = blockIdx.x;           // b*2 + hb
    const int b    = cta >> 1;
    const int base = (cta & 1) * EPC;
    const int lane = threadIdx.x;
    int* rows = g_rows + cta * MAXROWS;
    int row = 0;
#pragma unroll
    for (int k = 0; k < 2; ++k) {
        for (int i0 = 0; i0 < EPC; i0 += 32) {
            int i = i0 + lane;
            bool m = false; int meta = 0;
            if (i < EPC) {
                int e = base + i;
                int kk = graph[b*EDGES + e];
                int r = e / 49, j = e - r*49;
                int s = j + (j >= r);
                meta = (kk << 16) | (r << 8) | s;
                m = (kk == k);
            }
            unsigned mask = __ballot_sync(0xffffffffu, m);
            if (m) rows[row + __popc(mask & ((1u << lane) - 1u))] = meta;
            row += __popc(mask);
        }
        int pad = (128 - (row & 127)) & 127;
        for (int i = lane; i < pad; i += 32) rows[row + i] = -1;
        row += pad;
    }
    if (lane == 0) g_nrows[cta] = row;
}

// ---------------- edge kernel: fused gather + single-expert MLP + aggregate ----------------
__global__ void __launch_bounds__(256, 1)
edge_kernel(const float* __restrict__ b1,
            const float* __restrict__ b2) {
    extern __shared__ char smem_raw[];
    SmemA* sm = reinterpret_cast<SmemA*>(smem_raw);
    const int tid = threadIdx.x;
    const int cta = blockIdx.x;
    const int b   = cta >> 1;

    // load weights + y[b] + biases to SMEM
    {
        const uint4* src = reinterpret_cast<const uint4*>(g_Wt);
        uint4* dst = reinterpret_cast<uint4*>(&sm->W[0][0]);
        for (int i = tid; i < 4*HDIM*PS/8; i += 256) dst[i] = src[i];
    }
    {
        const uint4* src = reinterpret_cast<const uint4*>(g_ybf + b*NNODE*FDIM);
        uint4* dst = reinterpret_cast<uint4*>(&sm->y[0]);
        for (int i = tid; i < NNODE*FDIM/8; i += 256) dst[i] = src[i];
    }
    sm->B1[tid] = b1[tid];
    sm->B2[tid] = b2[tid];
    __syncthreads();

    const int lane = tid & 31, wid = tid >> 5;
    const int g = lane >> 2, tig = lane & 3;
    const int wm = (wid & 1) * 64;           // 2 warps along M
    const int wn = (wid >> 1) * 32;          // 4 warps along N
    const int nch = g_nrows[cta] >> 7;
    const int* __restrict__ rows = g_rows + cta * MAXROWS;

    for (int ch = 0; ch < nch; ++ch) {
        // row metadata (chunk is guaranteed single-type; first row always valid)
        if (tid < CHUNK) {
            int v = rows[ch*CHUNK + tid];
            sm->Rt[tid] = (v < 0) ? -1 : ((v >> 8) & 255);
            if (tid == 0) sm->ck = (v >> 16);
        }
        // build pre tile: [send feat | recv feat], 2 threads per row
        {
            int row = tid >> 1, hlf = tid & 1;
            int v = rows[ch*CHUNK + row];
            uint4* dst = reinterpret_cast<uint4*>(&sm->pre[row*PS + hlf*64]);
            if (v >= 0) {
                int node = hlf ? ((v >> 8) & 255) : (v & 255);
                const uint4* src = reinterpret_cast<const uint4*>(&sm->y[node*FDIM]);
#pragma unroll
                for (int q = 0; q < 8; ++q) dst[q] = src[q];
            } else {
                uint4 z = make_uint4(0,0,0,0);
#pragma unroll
                for (int q = 0; q < 8; ++q) dst[q] = z;
            }
        }
        __syncthreads();
        const int k = sm->ck;

        // ---- GEMM1: h = relu(pre @ W1[k] + b1[k]) ----
        {
            float C[16][4];
#pragma unroll
            for (int i = 0; i < 16; ++i)
#pragma unroll
                for (int q = 0; q < 4; ++q) C[i][q] = 0.f;

            gemm128(sm->pre, sm->W[k], C, wm, wn, g, tig);

#pragma unroll
            for (int mt = 0; mt < 4; ++mt)
#pragma unroll
                for (int nt = 0; nt < 4; ++nt) {
                    int r0 = wm + mt*16 + g, r1 = r0 + 8;
                    int c0 = wn + nt*8 + 2*tig;
                    float bias0 = sm->B1[k*HDIM + c0];
                    float bias1 = sm->B1[k*HDIM + c0 + 1];
                    float* c = C[mt*4 + nt];
                    *reinterpret_cast<uint32_t*>(&sm->hbuf[r0*PS + c0]) =
                        packbf(fmaxf(c[0] + bias0, 0.f), fmaxf(c[1] + bias1, 0.f));
                    *reinterpret_cast<uint32_t*>(&sm->hbuf[r1*PS + c0]) =
                        packbf(fmaxf(c[2] + bias0, 0.f), fmaxf(c[3] + bias1, 0.f));
                }
        }
        __syncthreads();

        // ---- GEMM2: m = relu(h @ W2[k] + b2[k]) -> pre buffer ----
        {
            float C[16][4];
#pragma unroll
            for (int i = 0; i < 16; ++i)
#pragma unroll
                for (int q = 0; q < 4; ++q) C[i][q] = 0.f;

            gemm128(sm->hbuf, sm->W[2 + k], C, wm, wn, g, tig);

#pragma unroll
            for (int mt = 0; mt < 4; ++mt)
#pragma unroll
                for (int nt = 0; nt < 4; ++nt) {
                    int r0 = wm + mt*16 + g, r1 = r0 + 8;
                    int c0 = wn + nt*8 + 2*tig;
                    float bias0 = sm->B2[k*HDIM + c0];
                    float bias1 = sm->B2[k*HDIM + c0 + 1];
                    float* c = C[mt*4 + nt];
                    *reinterpret_cast<uint32_t*>(&sm->pre[r0*PS + c0]) =
                        packbf(fmaxf(c[0] + bias0, 0.f), fmaxf(c[1] + bias1, 0.f));
                    *reinterpret_cast<uint32_t*>(&sm->pre[r1*PS + c0]) =
                        packbf(fmaxf(c[2] + bias0, 0.f), fmaxf(c[3] + bias1, 0.f));
                }
        }
        __syncthreads();

        // segmented aggregation over receiver runs (rows sorted by (type, receiver))
        {
            int colT = tid & 127;
            int rbeg = (tid < 128) ? 0 : 64;
            int rend = (tid < 128) ? 64 : 128;
            float acc = 0.f; int cur = -1;
            for (int row = rbeg; row < rend; ++row) {
                int rr = sm->Rt[row];
                if (rr != cur) {
                    if (cur >= 0) atomicAdd(&g_agg[(b*NNODE + cur)*HDIM + colT], acc);
                    acc = 0.f; cur = rr;
                }
                acc += __bfloat162float(sm->pre[row*PS + colT]);
            }
            if (cur >= 0) atomicAdd(&g_agg[(b*NNODE + cur)*HDIM + colT], acc);
        }
        __syncthreads();
    }
}

// ---------------- node kernel: tanh(agg*inv_n @ W3 + b3) + RK4 stage update ----------------
__global__ void __launch_bounds__(256)
node_kernel(const float* __restrict__ ts, int t, int stage,
            const float* __restrict__ W3, const float* __restrict__ b3,
            float* __restrict__ out) {
    __shared__ float sW3[HDIM*FDIM];
    __shared__ float sb3[FDIM];
    __shared__ float sAgg[8][HDIM];
    int tid = threadIdx.x;
    for (int i = tid; i < HDIM*FDIM; i += 256) sW3[i] = W3[i];
    if (tid < FDIM) sb3[tid] = b3[tid];
    __syncthreads();

    int lane = tid & 31, wid = tid >> 5;
    int node = blockIdx.x * 8 + wid;

#pragma unroll
    for (int i = 0; i < 4; ++i) {
        int idx = node*HDIM + lane + i*32;
        float v = g_agg[idx];
        g_agg[idx] = 0.f;                    // zero for next eval
        sAgg[wid][lane + i*32] = v;
    }
    __syncwarp();

    float dt = ts[t+1] - ts[t];
    const float inv_n = 1.0f / (float)NNODE;

#pragma unroll
    for (int hlf = 0; hlf < 2; ++hlf) {
        int jj = lane + hlf*32;
        float acc = 0.f;
#pragma unroll 16
        for (int hh = 0; hh < HDIM; ++hh)
            acc = fmaf(sAgg[wid][hh], sW3[hh*FDIM + jj], acc);
        float kv = tanhf(acc * inv_n + sb3[jj]);
        int idx = node*FDIM + jj;
        float yv = g_y[idx];
        float yin;
        if (stage == 0)      { g_ksum[idx] = kv;          yin = yv + 0.5f*dt*kv; }
        else if (stage == 1) { g_ksum[idx] += 2.f*kv;     yin = yv + 0.5f*dt*kv; }
        else if (stage == 2) { g_ksum[idx] += 2.f*kv;     yin = yv + dt*kv; }
        else {
            float yn = yv + dt*(1.f/6.f)*(g_ksum[idx] + kv);
            g_y[idx] = yn;
            out[node*(TSTEPS*FDIM) + (t+1)*FDIM + jj] = yn;
            yin = yn;
        }
        g_ybf[idx] = __float2bfloat16(yin);
    }
}

// ---------------- launcher ----------------
extern "C" void kernel_launch(void* const* d_in, const int* in_sizes, int n_in,
                              void* d_out, int out_size) {
    const float* fp    = (const float*)d_in[0];
    const float* ts    = (const float*)d_in[1];
    const int*   graph = (const int*)d_in[2];
    const float* W1    = (const float*)d_in[3];
    const float* b1    = (const float*)d_in[4];
    const float* W2    = (const float*)d_in[5];
    const float* b2    = (const float*)d_in[6];
    const float* W3    = (const float*)d_in[7];
    const float* b3    = (const float*)d_in[8];
    float* out = (float*)d_out;

    const size_t smem = sizeof(SmemA);
    cudaFuncSetAttribute(edge_kernel, cudaFuncAttributeMaxDynamicSharedMemorySize, (int)smem);

    prep_kernel<<<256, 256>>>(fp, W1, W2, out);
    sort_kernel<<<128, 32>>>(graph);
    for (int t = 0; t < TSTEPS - 1; ++t) {
        for (int st = 0; st < 4; ++st) {
            edge_kernel<<<128, 256, smem>>>(b1, b2);
            node_kernel<<<400, 256>>>(ts, t, st, W3, b3, out);
        }
    }
}